// round 1
// baseline (speedup 1.0000x reference)
#include <cuda_runtime.h>
#include <cuda_bf16.h>
#include <math.h>

#define DDIM 256
#define NQMAX 40000
#define BM 128
#define BN 128
#define BK 8

// ---------------- scratch (static device globals; no allocation) -------------
__device__ float g_v   [NQMAX * DDIM];   // value projection
__device__ float g_off [NQMAX * 96];     // sampling offsets
__device__ float g_attn[NQMAX * 48];     // attention logits
__device__ float g_msda[NQMAX * DDIM];   // msda output / ffn out
__device__ float g_tmp [NQMAX * DDIM];   // gemm staging / gelu hidden
__device__ float g_y   [NQMAX * DDIM];   // post-LN1 activations

// ---------------- packed fp32x2 helpers (Blackwell FFMA2) --------------------
__device__ __forceinline__ unsigned long long bcast2(float a) {
    unsigned long long r;
    asm("mov.b64 %0, {%1, %1};" : "=l"(r) : "f"(a));
    return r;
}
__device__ __forceinline__ void ffma2(unsigned long long& d, unsigned long long a,
                                      unsigned long long b) {
    asm("fma.rn.f32x2 %0, %1, %2, %0;" : "+l"(d) : "l"(a), "l"(b));
}
__device__ __forceinline__ float2 unpack2(unsigned long long v) {
    float2 f;
    asm("mov.b64 {%0, %1}, %2;" : "=f"(f.x), "=f"(f.y) : "l"(v));
    return f;
}

__device__ __forceinline__ float gelu_exact(float x) {
    return 0.5f * x * (1.0f + erff(x * 0.70710678118654752f));
}

// ---------------- generic GEMM: C = A(MxK) @ B(KxN) + bias, K = 256 ----------
// mode 0: +bias; mode 1: +bias then exact GELU
__global__ __launch_bounds__(256)
void gemm_kernel(const float* __restrict__ A, const float* __restrict__ B,
                 const float* __restrict__ bias, float* __restrict__ C,
                 int M, int N, int mode) {
    __shared__ __align__(16) float As[BK][BM];
    __shared__ __align__(16) float Bs[BK][BN];

    const int tid = threadIdx.x;
    const int m0 = blockIdx.y * BM;
    const int n0 = blockIdx.x * BN;

    const int aRow = tid >> 1;            // 0..127
    const int aCol = (tid & 1) * 4;       // 0 or 4
    const int bRow = tid >> 5;            // 0..7
    const int bCol = (tid & 31) * 4;      // 0..124

    const int tx = tid & 15;              // col group
    const int ty = tid >> 4;              // row group

    unsigned long long acc[8][4];
#pragma unroll
    for (int r = 0; r < 8; ++r)
#pragma unroll
        for (int j = 0; j < 4; ++j) acc[r][j] = 0ULL;

    float4 aReg, bReg;
    const int gm = m0 + aRow;
    const int gc = n0 + bCol;

    // prefetch tile 0
    {
        if (gm < M) aReg = *reinterpret_cast<const float4*>(A + (long)gm * DDIM + aCol);
        else        aReg = make_float4(0.f, 0.f, 0.f, 0.f);
        if (gc + 3 < N) {
            bReg = *reinterpret_cast<const float4*>(B + (long)bRow * N + gc);
        } else {
            bReg.x = (gc + 0 < N) ? B[(long)bRow * N + gc + 0] : 0.f;
            bReg.y = (gc + 1 < N) ? B[(long)bRow * N + gc + 1] : 0.f;
            bReg.z = (gc + 2 < N) ? B[(long)bRow * N + gc + 2] : 0.f;
            bReg.w = (gc + 3 < N) ? B[(long)bRow * N + gc + 3] : 0.f;
        }
    }

    const int numTiles = DDIM / BK;  // 32
    for (int t = 0; t < numTiles; ++t) {
        __syncthreads();
        As[aCol + 0][aRow] = aReg.x;
        As[aCol + 1][aRow] = aReg.y;
        As[aCol + 2][aRow] = aReg.z;
        As[aCol + 3][aRow] = aReg.w;
        *reinterpret_cast<float4*>(&Bs[bRow][bCol]) = bReg;
        __syncthreads();

        if (t + 1 < numTiles) {
            const int k1 = (t + 1) * BK;
            if (gm < M) aReg = *reinterpret_cast<const float4*>(A + (long)gm * DDIM + k1 + aCol);
            else        aReg = make_float4(0.f, 0.f, 0.f, 0.f);
            if (gc + 3 < N) {
                bReg = *reinterpret_cast<const float4*>(B + (long)(k1 + bRow) * N + gc);
            } else {
                bReg.x = (gc + 0 < N) ? B[(long)(k1 + bRow) * N + gc + 0] : 0.f;
                bReg.y = (gc + 1 < N) ? B[(long)(k1 + bRow) * N + gc + 1] : 0.f;
                bReg.z = (gc + 2 < N) ? B[(long)(k1 + bRow) * N + gc + 2] : 0.f;
                bReg.w = (gc + 3 < N) ? B[(long)(k1 + bRow) * N + gc + 3] : 0.f;
            }
        }

#pragma unroll
        for (int kk = 0; kk < BK; ++kk) {
            float4 a0 = *reinterpret_cast<const float4*>(&As[kk][ty * 8]);
            float4 a1 = *reinterpret_cast<const float4*>(&As[kk][ty * 8 + 4]);
            ulonglong2 b0 = *reinterpret_cast<const ulonglong2*>(&Bs[kk][tx * 8]);
            ulonglong2 b1 = *reinterpret_cast<const ulonglong2*>(&Bs[kk][tx * 8 + 4]);
            float ar[8] = {a0.x, a0.y, a0.z, a0.w, a1.x, a1.y, a1.z, a1.w};
#pragma unroll
            for (int r = 0; r < 8; ++r) {
                unsigned long long ap = bcast2(ar[r]);
                ffma2(acc[r][0], ap, b0.x);
                ffma2(acc[r][1], ap, b0.y);
                ffma2(acc[r][2], ap, b1.x);
                ffma2(acc[r][3], ap, b1.y);
            }
        }
    }

    // epilogue
    const int cb = n0 + tx * 8;
    const bool fullN = (n0 + BN <= N);
#pragma unroll
    for (int r = 0; r < 8; ++r) {
        const int row = m0 + ty * 8 + r;
        if (row >= M) continue;
        float o[8];
#pragma unroll
        for (int j = 0; j < 4; ++j) {
            float2 p = unpack2(acc[r][j]);
            o[2 * j]     = p.x;
            o[2 * j + 1] = p.y;
        }
        if (fullN) {
#pragma unroll
            for (int i = 0; i < 8; ++i) {
                o[i] += bias[cb + i];
                if (mode == 1) o[i] = gelu_exact(o[i]);
            }
            float4 v0 = make_float4(o[0], o[1], o[2], o[3]);
            float4 v1 = make_float4(o[4], o[5], o[6], o[7]);
            *reinterpret_cast<float4*>(C + (long)row * N + cb)     = v0;
            *reinterpret_cast<float4*>(C + (long)row * N + cb + 4) = v1;
        } else {
#pragma unroll
            for (int i = 0; i < 8; ++i) {
                const int c = cb + i;
                if (c < N) {
                    float vv = o[i] + bias[c];
                    if (mode == 1) vv = gelu_exact(vv);
                    C[(long)row * N + c] = vv;
                }
            }
        }
    }
}

// ---------------- MSDA sampling: one warp per (query, head) ------------------
__global__ __launch_bounds__(256)
void msda_sample_kernel(const float* __restrict__ off, const float* __restrict__ attnl,
                        const float* __restrict__ v, const float* __restrict__ ref,
                        const int* __restrict__ ss, float* __restrict__ out) {
    const int q = blockIdx.x;
    const int h = threadIdx.x >> 5;
    const int lane = threadIdx.x & 31;

    const int H = ss[0];
    const int W = ss[1];
    const float fW = (float)W, fH = (float)H;

    const float refx = __ldg(&ref[q * 2 + 0]);
    const float refy = __ldg(&ref[q * 2 + 1]);

    float lg[6];
    float mx = -1e30f;
#pragma unroll
    for (int p = 0; p < 6; ++p) {
        lg[p] = __ldg(&attnl[q * 48 + h * 6 + p]);
        mx = fmaxf(mx, lg[p]);
    }
    float s = 0.f;
#pragma unroll
    for (int p = 0; p < 6; ++p) {
        lg[p] = expf(lg[p] - mx);
        s += lg[p];
    }
    const float inv = 1.f / s;

    const float* vh = v + h * 32 + lane;
    float acc = 0.f;

#pragma unroll
    for (int p = 0; p < 6; ++p) {
        const float ox = __ldg(&off[q * 96 + h * 12 + p * 2 + 0]);
        const float oy = __ldg(&off[q * 96 + h * 12 + p * 2 + 1]);
        const float lx = (refx + ox / fW) * fW - 0.5f;
        const float ly = (refy + oy / fH) * fH - 0.5f;
        const float x0f = floorf(lx);
        const float y0f = floorf(ly);
        const int x0 = (int)x0f;
        const int y0 = (int)y0f;
        const float fx = lx - x0f;
        const float fy = ly - y0f;
        const float a = lg[p] * inv;
        const float w00 = (1.f - fx) * (1.f - fy) * a;
        const float w10 = fx * (1.f - fy) * a;
        const float w01 = (1.f - fx) * fy * a;
        const float w11 = fx * fy * a;
        const bool vx0 = (x0 >= 0) && (x0 < W);
        const bool vx1 = (x0 + 1 >= 0) && (x0 + 1 < W);
        const bool vy0 = (y0 >= 0) && (y0 < H);
        const bool vy1 = (y0 + 1 >= 0) && (y0 + 1 < H);
        if (vy0 && vx0) acc += w00 * __ldg(vh + (long)(y0 * W + x0) * DDIM);
        if (vy0 && vx1) acc += w10 * __ldg(vh + (long)(y0 * W + x0 + 1) * DDIM);
        if (vy1 && vx0) acc += w01 * __ldg(vh + (long)((y0 + 1) * W + x0) * DDIM);
        if (vy1 && vx1) acc += w11 * __ldg(vh + (long)((y0 + 1) * W + x0 + 1) * DDIM);
    }

    out[(long)q * DDIM + h * 32 + lane] = acc;
}

// ---------------- fused residual + LayerNorm (one block per row) -------------
__global__ __launch_bounds__(256)
void ln_kernel(const float* __restrict__ x, const float* __restrict__ res,
               const float* __restrict__ g, const float* __restrict__ b,
               float* __restrict__ out) {
    const int row = blockIdx.x;
    const int tid = threadIdx.x;
    const float v = x[(long)row * DDIM + tid] + res[(long)row * DDIM + tid];

    float s = v, s2 = v * v;
#pragma unroll
    for (int o = 16; o; o >>= 1) {
        s  += __shfl_xor_sync(0xffffffffu, s, o);
        s2 += __shfl_xor_sync(0xffffffffu, s2, o);
    }
    __shared__ float sh[16];
    const int w = tid >> 5, lane = tid & 31;
    if (lane == 0) { sh[w] = s; sh[w + 8] = s2; }
    __syncthreads();
    if (tid == 0) {
        float a = 0.f, c = 0.f;
#pragma unroll
        for (int i = 0; i < 8; ++i) { a += sh[i]; c += sh[i + 8]; }
        sh[0] = a; sh[8] = c;
    }
    __syncthreads();
    const float mean = sh[0] * (1.f / 256.f);
    const float var  = sh[8] * (1.f / 256.f) - mean * mean;
    const float rstd = rsqrtf(var + 1e-5f);
    out[(long)row * DDIM + tid] = (v - mean) * rstd * g[tid] + b[tid];
}

// ---------------- launch ------------------------------------------------------
extern "C" void kernel_launch(void* const* d_in, const int* in_sizes, int n_in,
                              void* d_out, int out_size) {
    const float* query  = (const float*)d_in[0];
    const float* value  = (const float*)d_in[1];
    const float* refp   = (const float*)d_in[2];
    const int*   ss     = (const int*)d_in[3];
    // d_in[4]: level_start_index (single level, 0) — unused
    const float* W_off  = (const float*)d_in[5];
    const float* b_off  = (const float*)d_in[6];
    const float* W_attn = (const float*)d_in[7];
    const float* b_attn = (const float*)d_in[8];
    const float* W_val  = (const float*)d_in[9];
    const float* b_val  = (const float*)d_in[10];
    const float* W_out  = (const float*)d_in[11];
    const float* b_out  = (const float*)d_in[12];
    const float* ln1_g  = (const float*)d_in[13];
    const float* ln1_b  = (const float*)d_in[14];
    const float* W1     = (const float*)d_in[15];
    const float* b1     = (const float*)d_in[16];
    const float* W2     = (const float*)d_in[17];
    const float* b2     = (const float*)d_in[18];
    const float* ln2_g  = (const float*)d_in[19];
    const float* ln2_b  = (const float*)d_in[20];
    float* out = (float*)d_out;

    const int M  = in_sizes[0] / DDIM;   // 40000 queries
    const int Mv = in_sizes[1] / DDIM;   // 40000 spatial positions

    float *pv, *poff, *pattn, *pmsda, *ptmp, *py;
    cudaGetSymbolAddress((void**)&pv,    g_v);
    cudaGetSymbolAddress((void**)&poff,  g_off);
    cudaGetSymbolAddress((void**)&pattn, g_attn);
    cudaGetSymbolAddress((void**)&pmsda, g_msda);
    cudaGetSymbolAddress((void**)&ptmp,  g_tmp);
    cudaGetSymbolAddress((void**)&py,    g_y);

    const int gM  = (M  + BM - 1) / BM;
    const int gMv = (Mv + BM - 1) / BM;

    // 1) value projection
    gemm_kernel<<<dim3(2, gMv), 256>>>(value, W_val, b_val, pv, Mv, DDIM, 0);
    // 2) sampling offsets + attention logits
    gemm_kernel<<<dim3(1, gM), 256>>>(query, W_off,  b_off,  poff,  M, 96, 0);
    gemm_kernel<<<dim3(1, gM), 256>>>(query, W_attn, b_attn, pattn, M, 48, 0);
    // 3) deformable sampling
    msda_sample_kernel<<<M, 256>>>(poff, pattn, pv, refp, ss, pmsda);
    // 4) output projection + residual + LN1
    gemm_kernel<<<dim3(2, gM), 256>>>(pmsda, W_out, b_out, ptmp, M, DDIM, 0);
    ln_kernel<<<M, 256>>>(ptmp, query, ln1_g, ln1_b, py);
    // 5) FFN: gelu(y@W1+b1)@W2+b2 + residual + LN2
    gemm_kernel<<<dim3(2, gM), 256>>>(py, W1, b1, ptmp, M, DDIM, 1);
    gemm_kernel<<<dim3(2, gM), 256>>>(ptmp, W2, b2, pmsda, M, DDIM, 0);
    ln_kernel<<<M, 256>>>(pmsda, py, ln2_g, ln2_b, out);
}

// round 3
// speedup vs baseline: 1.7447x; 1.7447x over previous
#include <cuda_runtime.h>
#include <cuda_bf16.h>
#include <math.h>
#include <stdint.h>

#define DDIM 256
#define NQMAX 40000

// ---------------- scratch (device globals; zero-initialized, no allocation) --
__device__ __align__(16) float g_v   [NQMAX * DDIM];
__device__ __align__(16) float g_oa  [NQMAX * 144];
__device__ __align__(16) float g_msda[NQMAX * DDIM];
__device__ __align__(16) float g_tmp [NQMAX * DDIM];
__device__ __align__(16) float g_y   [NQMAX * DDIM];

// transposed + bf16-split weights: [N][K=256]   (oa padded to 256 rows, zeros)
__device__ __align__(16) __nv_bfloat16 g_bv_h[DDIM * DDIM];
__device__ __align__(16) __nv_bfloat16 g_bv_l[DDIM * DDIM];
__device__ __align__(16) __nv_bfloat16 g_bo_h[DDIM * DDIM];
__device__ __align__(16) __nv_bfloat16 g_bo_l[DDIM * DDIM];
__device__ __align__(16) __nv_bfloat16 g_b1_h[DDIM * DDIM];
__device__ __align__(16) __nv_bfloat16 g_b1_l[DDIM * DDIM];
__device__ __align__(16) __nv_bfloat16 g_b2_h[DDIM * DDIM];
__device__ __align__(16) __nv_bfloat16 g_b2_l[DDIM * DDIM];
__device__ __align__(16) __nv_bfloat16 g_boa_h[DDIM * DDIM];
__device__ __align__(16) __nv_bfloat16 g_boa_l[DDIM * DDIM];
__device__ __align__(16) float g_boa[144];

// ---------------- helpers ------------------------------------------------------
__device__ __forceinline__ uint32_t smem_u32(const void* p) {
    uint32_t a;
    asm("{ .reg .u64 t; cvta.to.shared.u64 t, %1; cvt.u32.u64 %0, t; }" : "=r"(a) : "l"(p));
    return a;
}

__device__ __forceinline__ uint32_t pack_bf16(__nv_bfloat16 x, __nv_bfloat16 y) {
    __nv_bfloat162 t(x, y);
    return *reinterpret_cast<uint32_t*>(&t);
}

__device__ __forceinline__ float gelu_exact(float x) {
    return 0.5f * x * (1.0f + erff(x * 0.70710678118654752f));
}

#define LDSM4(r, addr) \
    asm volatile("ldmatrix.sync.aligned.m8n8.x4.shared.b16 {%0,%1,%2,%3}, [%4];" \
        : "=r"((r)[0]), "=r"((r)[1]), "=r"((r)[2]), "=r"((r)[3]) : "r"(addr))

__device__ __forceinline__ void mma_bf16(float* d, const uint32_t* a,
                                         uint32_t b0, uint32_t b1) {
    asm volatile(
        "mma.sync.aligned.m16n8k16.row.col.f32.bf16.bf16.f32 "
        "{%0,%1,%2,%3}, {%4,%5,%6,%7}, {%8,%9}, {%0,%1,%2,%3};"
        : "+f"(d[0]), "+f"(d[1]), "+f"(d[2]), "+f"(d[3])
        : "r"(a[0]), "r"(a[1]), "r"(a[2]), "r"(a[3]), "r"(b0), "r"(b1));
}

// ---------------- HMMA GEMM: C[M][N] = A[M][256] @ B^T + bias ------------------
// B pre-transposed hi/lo bf16 [>=128*gridX rows][256]. CTA tile 128x128.
// 8 warps: warp (wr=wid&3, wc=wid>>1... wc=wid>>2? -> 4x2) tile 32x64.
// MODE 0: +bias; MODE 1: +bias then exact GELU.
// smem: Ah[2][128*24], Al[2][..], Bh[2][..], Bl[2][..]  (rows padded to 24 bf16)
template<int MODE>
__global__ __launch_bounds__(256)
void gemm_mma(const float* __restrict__ A,
              const __nv_bfloat16* __restrict__ Bh,
              const __nv_bfloat16* __restrict__ Bl,
              const float* __restrict__ bias,
              float* __restrict__ C, int M, int N) {
    extern __shared__ __align__(128) char smem[];
    const uint32_t sb = smem_u32(smem);
    const int tid = threadIdx.x;
    const int wid = tid >> 5;
    const int lane = tid & 31;
    const int m0 = blockIdx.y * 128;
    const int n0 = blockIdx.x * 128;
    const int wr = wid & 3;        // 4 row-groups of 32
    const int wc = wid >> 2;       // 2 col-groups of 64

    constexpr int RB = 48;         // row bytes in smem (16 bf16 + 8 pad)
    constexpr int STG = 128 * RB;  // 6144 bytes per buffer
    const uint32_t offAh = 0, offAl = 2 * STG, offBh = 4 * STG, offBl = 6 * STG;

    float acc[2][8][4];
#pragma unroll
    for (int i = 0; i < 2; ++i)
#pragma unroll
        for (int j = 0; j < 8; ++j)
#pragma unroll
            for (int k = 0; k < 4; ++k) acc[i][j][k] = 0.f;

    // prefetch registers
    float4 pa[2];
    uint4 pbh, pbl;

    const int arow = tid >> 2;            // 0..63 base? no: tid>>2 -> 0..63
    // A: 128 rows x 4 float4 = 512 slots; thread handles slot tid and tid+256
    // B: 128 rows x 2 uint4 = 256 slots; thread handles slot tid
    const int brow = tid >> 1;
    const int bh8 = (tid & 1) * 8;

#define LOAD_CHUNK(c) do { \
    _Pragma("unroll") \
    for (int i = 0; i < 2; ++i) { \
        const int slot = tid + i * 256; \
        const int r = slot >> 2, q = slot & 3; \
        if (m0 + r < M) \
            pa[i] = *reinterpret_cast<const float4*>(A + (size_t)(m0 + r) * DDIM + (c) * 16 + q * 4); \
        else pa[i] = make_float4(0.f, 0.f, 0.f, 0.f); \
    } \
    pbh = *reinterpret_cast<const uint4*>(Bh + (size_t)(n0 + brow) * DDIM + (c) * 16 + bh8); \
    pbl = *reinterpret_cast<const uint4*>(Bl + (size_t)(n0 + brow) * DDIM + (c) * 16 + bh8); \
} while (0)

#define STORE_CHUNK(s) do { \
    _Pragma("unroll") \
    for (int i = 0; i < 2; ++i) { \
        const int slot = tid + i * 256; \
        const int r = slot >> 2, q = slot & 3; \
        __nv_bfloat16 h0 = __float2bfloat16(pa[i].x); \
        __nv_bfloat16 h1 = __float2bfloat16(pa[i].y); \
        __nv_bfloat16 h2 = __float2bfloat16(pa[i].z); \
        __nv_bfloat16 h3 = __float2bfloat16(pa[i].w); \
        uint2 hv = make_uint2(pack_bf16(h0, h1), pack_bf16(h2, h3)); \
        uint2 lv = make_uint2( \
            pack_bf16(__float2bfloat16(pa[i].x - __bfloat162float(h0)), \
                      __float2bfloat16(pa[i].y - __bfloat162float(h1))), \
            pack_bf16(__float2bfloat16(pa[i].z - __bfloat162float(h2)), \
                      __float2bfloat16(pa[i].w - __bfloat162float(h3)))); \
        *reinterpret_cast<uint2*>(smem + offAh + (s) * STG + r * RB + q * 8) = hv; \
        *reinterpret_cast<uint2*>(smem + offAl + (s) * STG + r * RB + q * 8) = lv; \
    } \
    *reinterpret_cast<uint4*>(smem + offBh + (s) * STG + brow * RB + bh8 * 2) = pbh; \
    *reinterpret_cast<uint4*>(smem + offBl + (s) * STG + brow * RB + bh8 * 2) = pbl; \
} while (0)

    LOAD_CHUNK(0);

    const uint32_t lmA = (wr * 32 + (lane & 15)) * RB + (lane >> 4) * 16;
    const uint32_t lmB = (wc * 64 + (lane & 15)) * RB + (lane >> 4) * 16;

    for (int c = 0; c < 16; ++c) {
        const int s = c & 1;
        STORE_CHUNK(s);
        __syncthreads();
        if (c < 15) LOAD_CHUNK(c + 1);

        uint32_t ah[2][4], al[2][4];
#pragma unroll
        for (int mr = 0; mr < 2; ++mr) {
            LDSM4(ah[mr], sb + offAh + s * STG + lmA + mr * 16 * RB);
            LDSM4(al[mr], sb + offAl + s * STG + lmA + mr * 16 * RB);
        }
        uint32_t bhf[4][4], blf[4][4];
#pragma unroll
        for (int nb = 0; nb < 4; ++nb) {
            LDSM4(bhf[nb], sb + offBh + s * STG + lmB + nb * 16 * RB);
            LDSM4(blf[nb], sb + offBl + s * STG + lmB + nb * 16 * RB);
        }

#pragma unroll
        for (int mr = 0; mr < 2; ++mr) {
#pragma unroll
            for (int nb = 0; nb < 4; ++nb) {
                mma_bf16(acc[mr][nb * 2 + 0], ah[mr], bhf[nb][0], bhf[nb][2]);
                mma_bf16(acc[mr][nb * 2 + 1], ah[mr], bhf[nb][1], bhf[nb][3]);
                mma_bf16(acc[mr][nb * 2 + 0], ah[mr], blf[nb][0], blf[nb][2]);
                mma_bf16(acc[mr][nb * 2 + 1], ah[mr], blf[nb][1], blf[nb][3]);
                mma_bf16(acc[mr][nb * 2 + 0], al[mr], bhf[nb][0], bhf[nb][2]);
                mma_bf16(acc[mr][nb * 2 + 1], al[mr], bhf[nb][1], bhf[nb][3]);
            }
        }
        __syncthreads();
    }

    // ---- epilogue: accums -> global with bias (+gelu) ----
#pragma unroll
    for (int mr = 0; mr < 2; ++mr) {
        const int r0 = m0 + wr * 32 + mr * 16 + (lane >> 2);
#pragma unroll
        for (int f = 0; f < 8; ++f) {
            const int col = n0 + wc * 64 + f * 8 + (lane & 3) * 2;
            if (col >= N) continue;
            const float b0 = bias[col], b1 = bias[col + 1];
#pragma unroll
            for (int h = 0; h < 2; ++h) {
                const int row = r0 + h * 8;
                if (row >= M) continue;
                float x0 = acc[mr][f][h * 2 + 0] + b0;
                float x1 = acc[mr][f][h * 2 + 1] + b1;
                if (MODE == 1) { x0 = gelu_exact(x0); x1 = gelu_exact(x1); }
                *reinterpret_cast<float2*>(C + (size_t)row * N + col) = make_float2(x0, x1);
            }
        }
    }
#undef LOAD_CHUNK
#undef STORE_CHUNK
}

// ---------------- weight transpose + bf16 split (once per launch) -------------
__global__ __launch_bounds__(256)
void convert_weights(const float* __restrict__ Wv, const float* __restrict__ Wo,
                     const float* __restrict__ W1, const float* __restrict__ W2,
                     const float* __restrict__ Woff, const float* __restrict__ Wattn,
                     const float* __restrict__ boff, const float* __restrict__ battn) {
    const int b = blockIdx.x;
    const int k = threadIdx.x;
    if (b == 1168) {
        if (k < 96) g_boa[k] = boff[k];
        else if (k < 144) g_boa[k] = battn[k - 96];
        return;
    }
    const float* W; __nv_bfloat16* oh; __nv_bfloat16* ol; int n, nout, N;
    if (b < 256)       { W = Wv; oh = g_bv_h; ol = g_bv_l; n = b;        nout = n; N = 256; }
    else if (b < 512)  { W = Wo; oh = g_bo_h; ol = g_bo_l; n = b - 256;  nout = n; N = 256; }
    else if (b < 768)  { W = W1; oh = g_b1_h; ol = g_b1_l; n = b - 512;  nout = n; N = 256; }
    else if (b < 1024) { W = W2; oh = g_b2_h; ol = g_b2_l; n = b - 768;  nout = n; N = 256; }
    else {
        nout = b - 1024;  // 0..143
        oh = g_boa_h; ol = g_boa_l;
        if (nout < 96) { W = Woff;  n = nout;      N = 96; }
        else           { W = Wattn; n = nout - 96; N = 48; }
    }
    const float x = W[(size_t)k * N + n];
    const __nv_bfloat16 h = __float2bfloat16(x);
    const __nv_bfloat16 l = __float2bfloat16(x - __bfloat162float(h));
    oh[(size_t)nout * DDIM + k] = h;
    ol[(size_t)nout * DDIM + k] = l;
}

// ---------------- MSDA sampling: one warp per (query, head) -------------------
__global__ __launch_bounds__(256)
void msda_sample_kernel(const float* __restrict__ oa, const float* __restrict__ v,
                        const float* __restrict__ ref, const int* __restrict__ ss,
                        float* __restrict__ out) {
    const int q = blockIdx.x;
    const int h = threadIdx.x >> 5;
    const int lane = threadIdx.x & 31;

    const int H = ss[0];
    const int W = ss[1];
    const float fW = (float)W, fH = (float)H;

    const float refx = __ldg(&ref[q * 2 + 0]);
    const float refy = __ldg(&ref[q * 2 + 1]);

    const float* qa = oa + (size_t)q * 144;
    float lg[6];
    float mx = -1e30f;
#pragma unroll
    for (int p = 0; p < 6; ++p) {
        lg[p] = __ldg(qa + 96 + h * 6 + p);
        mx = fmaxf(mx, lg[p]);
    }
    float s = 0.f;
#pragma unroll
    for (int p = 0; p < 6; ++p) { lg[p] = __expf(lg[p] - mx); s += lg[p]; }
    const float inv = 1.f / s;

    const float* vh = v + h * 32 + lane;
    float acc = 0.f;

#pragma unroll
    for (int p = 0; p < 6; ++p) {
        const float ox = __ldg(qa + h * 12 + p * 2 + 0);
        const float oy = __ldg(qa + h * 12 + p * 2 + 1);
        const float lx = (refx + ox / fW) * fW - 0.5f;
        const float ly = (refy + oy / fH) * fH - 0.5f;
        const float x0f = floorf(lx);
        const float y0f = floorf(ly);
        const int x0 = (int)x0f;
        const int y0 = (int)y0f;
        const float fx = lx - x0f;
        const float fy = ly - y0f;
        const float a = lg[p] * inv;
        const float w00 = (1.f - fx) * (1.f - fy) * a;
        const float w10 = fx * (1.f - fy) * a;
        const float w01 = (1.f - fx) * fy * a;
        const float w11 = fx * fy * a;
        const bool vx0 = (x0 >= 0) && (x0 < W);
        const bool vx1 = (x0 + 1 >= 0) && (x0 + 1 < W);
        const bool vy0 = (y0 >= 0) && (y0 < H);
        const bool vy1 = (y0 + 1 >= 0) && (y0 + 1 < H);
        if (vy0 && vx0) acc += w00 * __ldg(vh + (size_t)(y0 * W + x0) * DDIM);
        if (vy0 && vx1) acc += w10 * __ldg(vh + (size_t)(y0 * W + x0 + 1) * DDIM);
        if (vy1 && vx0) acc += w01 * __ldg(vh + (size_t)((y0 + 1) * W + x0) * DDIM);
        if (vy1 && vx1) acc += w11 * __ldg(vh + (size_t)((y0 + 1) * W + x0 + 1) * DDIM);
    }
    out[(size_t)q * DDIM + h * 32 + lane] = acc;
}

// ---------------- fused residual + LayerNorm -----------------------------------
__global__ __launch_bounds__(256)
void ln_kernel(const float* __restrict__ x, const float* __restrict__ res,
               const float* __restrict__ g, const float* __restrict__ b,
               float* __restrict__ out) {
    const int row = blockIdx.x;
    const int tid = threadIdx.x;
    const float v = x[(size_t)row * DDIM + tid] + res[(size_t)row * DDIM + tid];

    float s = v, s2 = v * v;
#pragma unroll
    for (int o = 16; o; o >>= 1) {
        s  += __shfl_xor_sync(0xffffffffu, s, o);
        s2 += __shfl_xor_sync(0xffffffffu, s2, o);
    }
    __shared__ float sh[16];
    const int w = tid >> 5, lane = tid & 31;
    if (lane == 0) { sh[w] = s; sh[w + 8] = s2; }
    __syncthreads();
    if (tid == 0) {
        float a = 0.f, c = 0.f;
#pragma unroll
        for (int i = 0; i < 8; ++i) { a += sh[i]; c += sh[i + 8]; }
        sh[0] = a; sh[8] = c;
    }
    __syncthreads();
    const float mean = sh[0] * (1.f / 256.f);
    const float var  = sh[8] * (1.f / 256.f) - mean * mean;
    const float rstd = rsqrtf(var + 1e-5f);
    out[(size_t)row * DDIM + tid] = (v - mean) * rstd * g[tid] + b[tid];
}

// ---------------- launch --------------------------------------------------------
extern "C" void kernel_launch(void* const* d_in, const int* in_sizes, int n_in,
                              void* d_out, int out_size) {
    const float* query  = (const float*)d_in[0];
    const float* value  = (const float*)d_in[1];
    const float* refp   = (const float*)d_in[2];
    const int*   ss     = (const int*)d_in[3];
    const float* W_off  = (const float*)d_in[5];
    const float* b_off  = (const float*)d_in[6];
    const float* W_attn = (const float*)d_in[7];
    const float* b_attn = (const float*)d_in[8];
    const float* W_val  = (const float*)d_in[9];
    const float* b_val  = (const float*)d_in[10];
    const float* W_out  = (const float*)d_in[11];
    const float* b_out  = (const float*)d_in[12];
    const float* ln1_g  = (const float*)d_in[13];
    const float* ln1_b  = (const float*)d_in[14];
    const float* W1     = (const float*)d_in[15];
    const float* b1     = (const float*)d_in[16];
    const float* W2     = (const float*)d_in[17];
    const float* b2     = (const float*)d_in[18];
    const float* ln2_g  = (const float*)d_in[19];
    const float* ln2_b  = (const float*)d_in[20];
    float* out = (float*)d_out;

    const int M  = in_sizes[0] / DDIM;
    const int Mv = in_sizes[1] / DDIM;

    float *pv, *poa, *pmsda, *ptmp, *py, *pboa;
    __nv_bfloat16 *bvh, *bvl, *boh, *bol, *b1h, *b1l, *b2h, *b2l, *boah, *boal;
    cudaGetSymbolAddress((void**)&pv,    g_v);
    cudaGetSymbolAddress((void**)&poa,   g_oa);
    cudaGetSymbolAddress((void**)&pmsda, g_msda);
    cudaGetSymbolAddress((void**)&ptmp,  g_tmp);
    cudaGetSymbolAddress((void**)&py,    g_y);
    cudaGetSymbolAddress((void**)&pboa,  g_boa);
    cudaGetSymbolAddress((void**)&bvh,   g_bv_h);
    cudaGetSymbolAddress((void**)&bvl,   g_bv_l);
    cudaGetSymbolAddress((void**)&boh,   g_bo_h);
    cudaGetSymbolAddress((void**)&bol,   g_bo_l);
    cudaGetSymbolAddress((void**)&b1h,   g_b1_h);
    cudaGetSymbolAddress((void**)&b1l,   g_b1_l);
    cudaGetSymbolAddress((void**)&b2h,   g_b2_h);
    cudaGetSymbolAddress((void**)&b2l,   g_b2_l);
    cudaGetSymbolAddress((void**)&boah,  g_boa_h);
    cudaGetSymbolAddress((void**)&boal,  g_boa_l);

    const int SMEM = 8 * 128 * 48;  // 49152 bytes
    cudaFuncSetAttribute(gemm_mma<0>, cudaFuncAttributeMaxDynamicSharedMemorySize, SMEM);
    cudaFuncSetAttribute(gemm_mma<1>, cudaFuncAttributeMaxDynamicSharedMemorySize, SMEM);

    const int gM  = (M + 127) / 128;
    const int gMv = (Mv + 127) / 128;

    // 0) weights -> transposed bf16 hi/lo
    convert_weights<<<1169, 256>>>(W_val, W_out, W1, W2, W_off, W_attn, b_off, b_attn);
    // 1) value projection
    gemm_mma<0><<<dim3(2, gMv), 256, SMEM>>>(value, bvh, bvl, b_val, pv, Mv, DDIM);
    // 2) fused offsets+attn logits GEMM (N=144)
    gemm_mma<0><<<dim3(2, gM), 256, SMEM>>>(query, boah, boal, pboa, poa, M, 144);
    // 3) deformable sampling
    msda_sample_kernel<<<M, 256>>>(poa, pv, refp, ss, pmsda);
    // 4) output projection + residual + LN1
    gemm_mma<0><<<dim3(2, gM), 256, SMEM>>>(pmsda, boh, bol, b_out, ptmp, M, DDIM);
    ln_kernel<<<M, 256>>>(ptmp, query, ln1_g, ln1_b, py);
    // 5) FFN
    gemm_mma<1><<<dim3(2, gM), 256, SMEM>>>(py, b1h, b1l, b1, ptmp, M, DDIM);
    gemm_mma<0><<<dim3(2, gM), 256, SMEM>>>(ptmp, b2h, b2l, b2, pmsda, M, DDIM);
    ln_kernel<<<M, 256>>>(pmsda, py, ln2_g, ln2_b, out);
}

// round 4
// speedup vs baseline: 1.9856x; 1.1381x over previous
#include <cuda_runtime.h>
#include <cuda_bf16.h>
#include <math.h>
#include <stdint.h>

#define DDIM 256
#define NQMAX 40000

// ---------------- scratch (device globals; zero-initialized, no allocation) --
__device__ __align__(16) float g_v   [NQMAX * DDIM];
__device__ __align__(16) float g_oa  [NQMAX * 144];
__device__ __align__(16) float g_msda[NQMAX * DDIM];
__device__ __align__(16) float g_tmp [NQMAX * DDIM];
__device__ __align__(16) float g_y   [NQMAX * DDIM];

// transposed + bf16-split weights: [N][K=256]   (oa padded to 256 rows, zeros)
__device__ __align__(16) __nv_bfloat16 g_bv_h[DDIM * DDIM];
__device__ __align__(16) __nv_bfloat16 g_bv_l[DDIM * DDIM];
__device__ __align__(16) __nv_bfloat16 g_bo_h[DDIM * DDIM];
__device__ __align__(16) __nv_bfloat16 g_bo_l[DDIM * DDIM];
__device__ __align__(16) __nv_bfloat16 g_b1_h[DDIM * DDIM];
__device__ __align__(16) __nv_bfloat16 g_b1_l[DDIM * DDIM];
__device__ __align__(16) __nv_bfloat16 g_b2_h[DDIM * DDIM];
__device__ __align__(16) __nv_bfloat16 g_b2_l[DDIM * DDIM];
__device__ __align__(16) __nv_bfloat16 g_boa_h[DDIM * DDIM];
__device__ __align__(16) __nv_bfloat16 g_boa_l[DDIM * DDIM];
__device__ __align__(16) float g_boa[144];

// ---------------- helpers ------------------------------------------------------
__device__ __forceinline__ uint32_t smem_u32(const void* p) {
    uint32_t a;
    asm("{ .reg .u64 t; cvta.to.shared.u64 t, %1; cvt.u32.u64 %0, t; }" : "=r"(a) : "l"(p));
    return a;
}

__device__ __forceinline__ uint32_t pack_bf16(__nv_bfloat16 x, __nv_bfloat16 y) {
    __nv_bfloat162 t(x, y);
    return *reinterpret_cast<uint32_t*>(&t);
}

__device__ __forceinline__ float gelu_exact(float x) {
    return 0.5f * x * (1.0f + erff(x * 0.70710678118654752f));
}

#define LDSM4(r, addr) \
    asm volatile("ldmatrix.sync.aligned.m8n8.x4.shared.b16 {%0,%1,%2,%3}, [%4];" \
        : "=r"((r)[0]), "=r"((r)[1]), "=r"((r)[2]), "=r"((r)[3]) : "r"(addr))

#define CP_ASYNC16(dst, src) \
    asm volatile("cp.async.ca.shared.global [%0], [%1], 16;" :: "r"(dst), "l"(src))
#define CP_COMMIT() asm volatile("cp.async.commit_group;" ::: "memory")
#define CP_WAIT(n)  asm volatile("cp.async.wait_group %0;" :: "n"(n) : "memory")

__device__ __forceinline__ void mma_bf16(float* d, const uint32_t* a,
                                         uint32_t b0, uint32_t b1) {
    asm volatile(
        "mma.sync.aligned.m16n8k16.row.col.f32.bf16.bf16.f32 "
        "{%0,%1,%2,%3}, {%4,%5,%6,%7}, {%8,%9}, {%0,%1,%2,%3};"
        : "+f"(d[0]), "+f"(d[1]), "+f"(d[2]), "+f"(d[3])
        : "r"(a[0]), "r"(a[1]), "r"(a[2]), "r"(a[3]), "r"(b0), "r"(b1));
}

// ---------------- HMMA GEMM: C[M][N] = A[M][256] @ B^T + bias ------------------
// B pre-transposed hi/lo bf16 [N_pad][256]; B loaded via cp.async.
// CTA tile 128x128, 8 warps (4x2), warp tile 32x64. MODE 1: +bias then GELU.
template<int MODE>
__global__ __launch_bounds__(256, 2)
void gemm_mma(const float* __restrict__ A,
              const __nv_bfloat16* __restrict__ Bh,
              const __nv_bfloat16* __restrict__ Bl,
              const float* __restrict__ bias,
              float* __restrict__ C, int M, int N) {
    extern __shared__ __align__(128) char smem[];
    const uint32_t sb = smem_u32(smem);
    const int tid = threadIdx.x;
    const int wid = tid >> 5;
    const int lane = tid & 31;
    const int m0 = blockIdx.y * 128;
    const int n0 = blockIdx.x * 128;
    const int wr = wid & 3;
    const int wc = wid >> 2;

    constexpr int RB = 48;         // smem row bytes (16 bf16 + 8 pad)
    constexpr int STG = 128 * RB;  // 6144 bytes per buffer
    const uint32_t offAh = 0, offAl = 2 * STG, offBh = 4 * STG, offBl = 6 * STG;

    float acc[2][8][4];
#pragma unroll
    for (int i = 0; i < 2; ++i)
#pragma unroll
        for (int j = 0; j < 8; ++j)
#pragma unroll
            for (int k = 0; k < 4; ++k) acc[i][j][k] = 0.f;

    float4 pa[2];
    const int brow = tid >> 1;
    const int bcol = (tid & 1) * 16;         // byte offset within 32B half-row pair
    const __nv_bfloat16* bSrcH = Bh + (size_t)(n0 + brow) * DDIM + (tid & 1) * 8;
    const __nv_bfloat16* bSrcL = Bl + (size_t)(n0 + brow) * DDIM + (tid & 1) * 8;
    const uint32_t bDstOff = brow * RB + bcol;

#define ISSUE_B(c, s) do { \
    CP_ASYNC16(sb + offBh + (s) * STG + bDstOff, bSrcH + (c) * 16); \
    CP_ASYNC16(sb + offBl + (s) * STG + bDstOff, bSrcL + (c) * 16); \
    CP_COMMIT(); } while (0)

#define LOAD_A(c) do { \
    _Pragma("unroll") \
    for (int i = 0; i < 2; ++i) { \
        const int slot = tid + i * 256; \
        const int r = slot >> 2, qq = slot & 3; \
        if (m0 + r < M) \
            pa[i] = *reinterpret_cast<const float4*>(A + (size_t)(m0 + r) * DDIM + (c) * 16 + qq * 4); \
        else pa[i] = make_float4(0.f, 0.f, 0.f, 0.f); \
    } } while (0)

#define STORE_A(s) do { \
    _Pragma("unroll") \
    for (int i = 0; i < 2; ++i) { \
        const int slot = tid + i * 256; \
        const int r = slot >> 2, qq = slot & 3; \
        __nv_bfloat16 h0 = __float2bfloat16(pa[i].x); \
        __nv_bfloat16 h1 = __float2bfloat16(pa[i].y); \
        __nv_bfloat16 h2 = __float2bfloat16(pa[i].z); \
        __nv_bfloat16 h3 = __float2bfloat16(pa[i].w); \
        uint2 hv = make_uint2(pack_bf16(h0, h1), pack_bf16(h2, h3)); \
        uint2 lv = make_uint2( \
            pack_bf16(__float2bfloat16(pa[i].x - __bfloat162float(h0)), \
                      __float2bfloat16(pa[i].y - __bfloat162float(h1))), \
            pack_bf16(__float2bfloat16(pa[i].z - __bfloat162float(h2)), \
                      __float2bfloat16(pa[i].w - __bfloat162float(h3)))); \
        *reinterpret_cast<uint2*>(smem + offAh + (s) * STG + r * RB + qq * 8) = hv; \
        *reinterpret_cast<uint2*>(smem + offAl + (s) * STG + r * RB + qq * 8) = lv; \
    } } while (0)

    ISSUE_B(0, 0);
    LOAD_A(0);

    const uint32_t lmA = (wr * 32 + (lane & 15)) * RB + (lane >> 4) * 16;
    const uint32_t lmB = (wc * 64 + (lane & 15)) * RB + (lane >> 4) * 16;

    for (int c = 0; c < 16; ++c) {
        const int s = c & 1;
        STORE_A(s);
        if (c < 15) { ISSUE_B(c + 1, s ^ 1); CP_WAIT(1); }
        else        { CP_WAIT(0); }
        __syncthreads();
        if (c < 15) LOAD_A(c + 1);

        uint32_t ah[2][4], al[2][4];
#pragma unroll
        for (int mr = 0; mr < 2; ++mr) {
            LDSM4(ah[mr], sb + offAh + s * STG + lmA + mr * 16 * RB);
            LDSM4(al[mr], sb + offAl + s * STG + lmA + mr * 16 * RB);
        }
#pragma unroll
        for (int nb = 0; nb < 4; ++nb) {
            uint32_t bh[4], bl[4];
            LDSM4(bh, sb + offBh + s * STG + lmB + nb * 16 * RB);
            LDSM4(bl, sb + offBl + s * STG + lmB + nb * 16 * RB);
#pragma unroll
            for (int mr = 0; mr < 2; ++mr) {
                mma_bf16(acc[mr][nb * 2 + 0], ah[mr], bh[0], bh[2]);
                mma_bf16(acc[mr][nb * 2 + 1], ah[mr], bh[1], bh[3]);
                mma_bf16(acc[mr][nb * 2 + 0], ah[mr], bl[0], bl[2]);
                mma_bf16(acc[mr][nb * 2 + 1], ah[mr], bl[1], bl[3]);
                mma_bf16(acc[mr][nb * 2 + 0], al[mr], bh[0], bh[2]);
                mma_bf16(acc[mr][nb * 2 + 1], al[mr], bh[1], bh[3]);
            }
        }
        __syncthreads();
    }

    // ---- epilogue ----
#pragma unroll
    for (int mr = 0; mr < 2; ++mr) {
        const int r0 = m0 + wr * 32 + mr * 16 + (lane >> 2);
#pragma unroll
        for (int f = 0; f < 8; ++f) {
            const int col = n0 + wc * 64 + f * 8 + (lane & 3) * 2;
            if (col >= N) continue;
            const float b0 = bias[col], b1 = bias[col + 1];
#pragma unroll
            for (int h = 0; h < 2; ++h) {
                const int row = r0 + h * 8;
                if (row >= M) continue;
                float x0 = acc[mr][f][h * 2 + 0] + b0;
                float x1 = acc[mr][f][h * 2 + 1] + b1;
                if (MODE == 1) { x0 = gelu_exact(x0); x1 = gelu_exact(x1); }
                *reinterpret_cast<float2*>(C + (size_t)row * N + col) = make_float2(x0, x1);
            }
        }
    }
#undef ISSUE_B
#undef LOAD_A
#undef STORE_A
}

// ---------------- weight transpose + bf16 split (once per launch) -------------
__global__ __launch_bounds__(256)
void convert_weights(const float* __restrict__ Wv, const float* __restrict__ Wo,
                     const float* __restrict__ W1, const float* __restrict__ W2,
                     const float* __restrict__ Woff, const float* __restrict__ Wattn,
                     const float* __restrict__ boff, const float* __restrict__ battn) {
    const int b = blockIdx.x;
    const int k = threadIdx.x;
    if (b == 1168) {
        if (k < 96) g_boa[k] = boff[k];
        else if (k < 144) g_boa[k] = battn[k - 96];
        return;
    }
    const float* W; __nv_bfloat16* oh; __nv_bfloat16* ol; int n, nout, N;
    if (b < 256)       { W = Wv; oh = g_bv_h; ol = g_bv_l; n = b;        nout = n; N = 256; }
    else if (b < 512)  { W = Wo; oh = g_bo_h; ol = g_bo_l; n = b - 256;  nout = n; N = 256; }
    else if (b < 768)  { W = W1; oh = g_b1_h; ol = g_b1_l; n = b - 512;  nout = n; N = 256; }
    else if (b < 1024) { W = W2; oh = g_b2_h; ol = g_b2_l; n = b - 768;  nout = n; N = 256; }
    else {
        nout = b - 1024;  // 0..143
        oh = g_boa_h; ol = g_boa_l;
        if (nout < 96) { W = Woff;  n = nout;      N = 96; }
        else           { W = Wattn; n = nout - 96; N = 48; }
    }
    const float x = W[(size_t)k * N + n];
    const __nv_bfloat16 h = __float2bfloat16(x);
    const __nv_bfloat16 l = __float2bfloat16(x - __bfloat162float(h));
    oh[(size_t)nout * DDIM + k] = h;
    ol[(size_t)nout * DDIM + k] = l;
}

// ---------------- MSDA sampling v2: corner-parallel float4 gathers ------------
// One warp per (query, head). 4 lane-groups of 8: group = bilinear corner;
// lane handles 4 channels (float4). Corners reduced with butterfly shuffles.
__global__ __launch_bounds__(256)
void msda_sample_kernel(const float* __restrict__ oa, const float* __restrict__ v,
                        const float* __restrict__ ref, const int* __restrict__ ss,
                        float* __restrict__ out) {
    const int q = blockIdx.x;
    const int h = threadIdx.x >> 5;
    const int lane = threadIdx.x & 31;
    const int corner = lane >> 3;       // 0..3
    const int dx = corner & 1;
    const int dy = corner >> 1;
    const int cg = lane & 7;            // channel group (4 floats)

    const int H = ss[0];
    const int W = ss[1];

    const float bx = __ldg(ref + q * 2 + 0) * (float)W - 0.5f;
    const float by = __ldg(ref + q * 2 + 1) * (float)H - 0.5f;

    const float* qa = oa + (size_t)q * 144;
    float lg[6];
    float mx = -1e30f;
#pragma unroll
    for (int p = 0; p < 6; ++p) {
        lg[p] = __ldg(qa + 96 + h * 6 + p);
        mx = fmaxf(mx, lg[p]);
    }
    float s = 0.f;
#pragma unroll
    for (int p = 0; p < 6; ++p) { lg[p] = __expf(lg[p] - mx); s += lg[p]; }
    const float inv = 1.f / s;

    const float4* vh = reinterpret_cast<const float4*>(v) + h * 8 + cg;  // row stride 64
    float4 acc = make_float4(0.f, 0.f, 0.f, 0.f);

#pragma unroll
    for (int p = 0; p < 6; ++p) {
        const float ox = __ldg(qa + h * 12 + p * 2 + 0);
        const float oy = __ldg(qa + h * 12 + p * 2 + 1);
        const float lx = bx + ox;
        const float ly = by + oy;
        const float x0f = floorf(lx);
        const float y0f = floorf(ly);
        const float fx = lx - x0f;
        const float fy = ly - y0f;
        const int xi = (int)x0f + dx;
        const int yi = (int)y0f + dy;
        const float wx = dx ? fx : 1.f - fx;
        const float wy = dy ? fy : 1.f - fy;
        const bool valid = (xi >= 0) & (xi < W) & (yi >= 0) & (yi < H);
        const float w = valid ? (lg[p] * inv) * wx * wy : 0.f;
        const int xc = min(max(xi, 0), W - 1);
        const int yc = min(max(yi, 0), H - 1);
        const float4 val = __ldg(vh + (size_t)(yc * W + xc) * 64);
        acc.x += w * val.x;
        acc.y += w * val.y;
        acc.z += w * val.z;
        acc.w += w * val.w;
    }

    // reduce the 4 corner groups
#pragma unroll
    for (int o = 8; o <= 16; o <<= 1) {
        acc.x += __shfl_xor_sync(0xffffffffu, acc.x, o);
        acc.y += __shfl_xor_sync(0xffffffffu, acc.y, o);
        acc.z += __shfl_xor_sync(0xffffffffu, acc.z, o);
        acc.w += __shfl_xor_sync(0xffffffffu, acc.w, o);
    }
    if (lane < 8)
        *reinterpret_cast<float4*>(out + (size_t)q * DDIM + h * 32 + cg * 4) = acc;
}

// ---------------- fused residual + LayerNorm -----------------------------------
__global__ __launch_bounds__(256)
void ln_kernel(const float* __restrict__ x, const float* __restrict__ res,
               const float* __restrict__ g, const float* __restrict__ b,
               float* __restrict__ out) {
    const int row = blockIdx.x;
    const int tid = threadIdx.x;
    const float v = x[(size_t)row * DDIM + tid] + res[(size_t)row * DDIM + tid];

    float s = v, s2 = v * v;
#pragma unroll
    for (int o = 16; o; o >>= 1) {
        s  += __shfl_xor_sync(0xffffffffu, s, o);
        s2 += __shfl_xor_sync(0xffffffffu, s2, o);
    }
    __shared__ float sh[16];
    const int w = tid >> 5, lane = tid & 31;
    if (lane == 0) { sh[w] = s; sh[w + 8] = s2; }
    __syncthreads();
    if (tid == 0) {
        float a = 0.f, c = 0.f;
#pragma unroll
        for (int i = 0; i < 8; ++i) { a += sh[i]; c += sh[i + 8]; }
        sh[0] = a; sh[8] = c;
    }
    __syncthreads();
    const float mean = sh[0] * (1.f / 256.f);
    const float var  = sh[8] * (1.f / 256.f) - mean * mean;
    const float rstd = rsqrtf(var + 1e-5f);
    out[(size_t)row * DDIM + tid] = (v - mean) * rstd * g[tid] + b[tid];
}

// ---------------- launch --------------------------------------------------------
extern "C" void kernel_launch(void* const* d_in, const int* in_sizes, int n_in,
                              void* d_out, int out_size) {
    const float* query  = (const float*)d_in[0];
    const float* value  = (const float*)d_in[1];
    const float* refp   = (const float*)d_in[2];
    const int*   ss     = (const int*)d_in[3];
    const float* W_off  = (const float*)d_in[5];
    const float* b_off  = (const float*)d_in[6];
    const float* W_attn = (const float*)d_in[7];
    const float* b_attn = (const float*)d_in[8];
    const float* W_val  = (const float*)d_in[9];
    const float* b_val  = (const float*)d_in[10];
    const float* W_out  = (const float*)d_in[11];
    const float* b_out  = (const float*)d_in[12];
    const float* ln1_g  = (const float*)d_in[13];
    const float* ln1_b  = (const float*)d_in[14];
    const float* W1     = (const float*)d_in[15];
    const float* b1     = (const float*)d_in[16];
    const float* W2     = (const float*)d_in[17];
    const float* b2     = (const float*)d_in[18];
    const float* ln2_g  = (const float*)d_in[19];
    const float* ln2_b  = (const float*)d_in[20];
    float* out = (float*)d_out;

    const int M  = in_sizes[0] / DDIM;
    const int Mv = in_sizes[1] / DDIM;

    float *pv, *poa, *pmsda, *ptmp, *py, *pboa;
    __nv_bfloat16 *bvh, *bvl, *boh, *bol, *b1h, *b1l, *b2h, *b2l, *boah, *boal;
    cudaGetSymbolAddress((void**)&pv,    g_v);
    cudaGetSymbolAddress((void**)&poa,   g_oa);
    cudaGetSymbolAddress((void**)&pmsda, g_msda);
    cudaGetSymbolAddress((void**)&ptmp,  g_tmp);
    cudaGetSymbolAddress((void**)&py,    g_y);
    cudaGetSymbolAddress((void**)&pboa,  g_boa);
    cudaGetSymbolAddress((void**)&bvh,   g_bv_h);
    cudaGetSymbolAddress((void**)&bvl,   g_bv_l);
    cudaGetSymbolAddress((void**)&boh,   g_bo_h);
    cudaGetSymbolAddress((void**)&bol,   g_bo_l);
    cudaGetSymbolAddress((void**)&b1h,   g_b1_h);
    cudaGetSymbolAddress((void**)&b1l,   g_b1_l);
    cudaGetSymbolAddress((void**)&b2h,   g_b2_h);
    cudaGetSymbolAddress((void**)&b2l,   g_b2_l);
    cudaGetSymbolAddress((void**)&boah,  g_boa_h);
    cudaGetSymbolAddress((void**)&boal,  g_boa_l);

    const int SMEM = 8 * 128 * 48;  // 49152 bytes
    cudaFuncSetAttribute(gemm_mma<0>, cudaFuncAttributeMaxDynamicSharedMemorySize, SMEM);
    cudaFuncSetAttribute(gemm_mma<1>, cudaFuncAttributeMaxDynamicSharedMemorySize, SMEM);

    const int gM  = (M + 127) / 128;
    const int gMv = (Mv + 127) / 128;

    // 0) weights -> transposed bf16 hi/lo
    convert_weights<<<1169, 256>>>(W_val, W_out, W1, W2, W_off, W_attn, b_off, b_attn);
    // 1) value projection
    gemm_mma<0><<<dim3(2, gMv), 256, SMEM>>>(value, bvh, bvl, b_val, pv, Mv, DDIM);
    // 2) fused offsets+attn logits GEMM (N=144)
    gemm_mma<0><<<dim3(2, gM), 256, SMEM>>>(query, boah, boal, pboa, poa, M, 144);
    // 3) deformable sampling
    msda_sample_kernel<<<M, 256>>>(poa, pv, refp, ss, pmsda);
    // 4) output projection + residual + LN1
    gemm_mma<0><<<dim3(2, gM), 256, SMEM>>>(pmsda, boh, bol, b_out, ptmp, M, DDIM);
    ln_kernel<<<M, 256>>>(ptmp, query, ln1_g, ln1_b, py);
    // 5) FFN
    gemm_mma<1><<<dim3(2, gM), 256, SMEM>>>(py, b1h, b1l, b1, ptmp, M, DDIM);
    gemm_mma<0><<<dim3(2, gM), 256, SMEM>>>(ptmp, b2h, b2l, b2, pmsda, M, DDIM);
    ln_kernel<<<M, 256>>>(pmsda, py, ln2_g, ln2_b, out);
}